// round 15
// baseline (speedup 1.0000x reference)
#include <cuda_runtime.h>
#include <cuda_bf16.h>
#include <cuda_fp16.h>
#include <cstdint>

#define N_NODES 50000
#define N_EDGES 800000
#define IN_CH   256
#define OUT_CH  64
#define NEG_SLOPE 0.2f
#define NB_SCAN 196   // ceil(N_NODES/256)

// dynamic smem layout (uint4 units): sX[8192] (128KB) | sB[64][68] (68KB) | mbar[8]
#define SX_U4     8192
#define SB_U4     (64 * 68)
#define DYN_BYTES (SX_U4 * 16 + SB_U4 * 16 + 64)   // 200768

// ---------------- scratch (device globals; no allocations allowed) -------------
__device__ float    g_feature[N_NODES * OUT_CH];   // fp32 features (self term)
__device__ uint32_t g_feath[N_NODES * 32];         // fp16x2 features (messages)
__device__ float    g_e0[N_NODES];
__device__ float    g_e1[N_NODES];
__device__ float    g_es[N_NODES];                 // exp(self logit)
__device__ uint4    g_Wi[2 * 64 * 32];             // [half][n][kc*4+tig]
__device__ int      g_cnt[N_NODES];
__device__ int      g_rowptr[N_NODES + 1];
__device__ int      g_cursor[N_NODES];
__device__ int      g_csrc[N_EDGES];
__device__ int      g_bsum[NB_SCAN];

__device__ __forceinline__ float lrelu(float v) {
    return v > 0.0f ? v : NEG_SLOPE * v;
}
__device__ __forceinline__ uint32_t smem_u32(const void* p) {
    uint32_t a;
    asm("{ .reg .u64 t; cvta.to.shared.u64 t, %1; cvt.u32.u64 %0, t; }" : "=r"(a) : "l"(p));
    return a;
}

// pack two floats (even, odd) into bf16x2 (even in low half)
__device__ __forceinline__ uint32_t pack_bf16(float e, float o) {
    uint32_t d;
    asm("cvt.rn.bf16x2.f32 %0, %1, %2;" : "=r"(d) : "f"(o), "f"(e));
    return d;
}
__device__ __forceinline__ float bf16lo_val(uint32_t w) { return __uint_as_float(w << 16); }
__device__ __forceinline__ float bf16hi_val(uint32_t w) { return __uint_as_float(w & 0xFFFF0000u); }

// pack two floats (even, odd) into fp16x2 (even in low half)
__device__ __forceinline__ uint32_t pack_f16(float e, float o) {
    uint32_t d;
    asm("cvt.rn.f16x2.f32 %0, %1, %2;" : "=r"(d) : "f"(o), "f"(e));
    return d;
}

// m16n8k16 row.col bf16 HMMA (target-generic; tcgen05 unavailable on this build)
__device__ __forceinline__ void mma_bf16(float* c, const uint32_t* a, uint32_t b0, uint32_t b1) {
    asm volatile(
        "mma.sync.aligned.m16n8k16.row.col.f32.bf16.bf16.f32 "
        "{%0,%1,%2,%3}, {%4,%5,%6,%7}, {%8,%9}, {%0,%1,%2,%3};"
        : "+f"(c[0]), "+f"(c[1]), "+f"(c[2]), "+f"(c[3])
        : "r"(a[0]), "r"(a[1]), "r"(a[2]), "r"(a[3]), "r"(b0), "r"(b1));
}

// ------------- K0a: W -> interleaved bf16 hi/lo quads --------------------------
__global__ __launch_bounds__(256) void k_wconv(const float* __restrict__ W) {
    int idx = blockIdx.x * 256 + threadIdx.x;    // 0..4095
    int half = idx >> 11, rem = idx & 2047;
    int n = rem >> 5, m = rem & 31;
    int kc = m >> 2, tig = m & 3;
    int kw = kc * 8 + tig;
    int k1 = half * 128 + 2 * kw;
    int k2 = k1 + 8;
    float a0 = W[n * 256 + k1], a1 = W[n * 256 + k1 + 1];
    float b0 = W[n * 256 + k2], b1 = W[n * 256 + k2 + 1];
    uint32_t h1 = pack_bf16(a0, a1);
    uint32_t h2 = pack_bf16(b0, b1);
    uint32_t l1 = pack_bf16(a0 - bf16lo_val(h1), a1 - bf16hi_val(h1));
    uint32_t l2 = pack_bf16(b0 - bf16lo_val(h2), b1 - bf16hi_val(h2));
    g_Wi[half * 2048 + n * 32 + m] = make_uint4(h1, h2, l1, l2);
}

// ------------- K0b: zero in-degree histogram -----------------------------------
__global__ __launch_bounds__(256) void k_zero() {
    int i = blockIdx.x * 256 + threadIdx.x;
    if (i < N_NODES) g_cnt[i] = 0;
}

// ------------- K1: HMMA projection, cp.async.bulk x staging --------------------
__global__ __launch_bounds__(256) void k_gemm_tc(const float* __restrict__ x,
                                                 const float* __restrict__ b,
                                                 const float* __restrict__ att) {
    extern __shared__ __align__(16) uint4 dyn4[];
    float*    sXf  = (float*)dyn4;                       // [8 warps][16 rows][256]
    uint4*    sB4  = dyn4 + SX_U4;                       // [n][68]
    uint64_t* mbar = (uint64_t*)(dyn4 + SX_U4 + SB_U4);  // [8]

    const int tid  = threadIdx.x;
    const int wid  = tid >> 5;
    const int lane = tid & 31;
    const int g    = lane >> 2;
    const int tig  = lane & 3;

    const int base = min(blockIdx.x * 128 + wid * 16, N_NODES - 16);
    const int r0 = base + g;
    const int r1 = base + g + 8;

    if (tid < 8) {
        asm volatile("mbarrier.init.shared.b64 [%0], 1;"
                     :: "r"(smem_u32(&mbar[tid])) : "memory");
    }
    __syncthreads();

    if (lane == 0) {
        uint32_t mb  = smem_u32(&mbar[wid]);
        uint32_t dst = smem_u32(sXf) + (uint32_t)wid * 16384u;
        const float* src = x + (size_t)base * IN_CH;
        asm volatile("mbarrier.arrive.expect_tx.shared.b64 _, [%0], %1;"
                     :: "r"(mb), "r"(16384u) : "memory");
        asm volatile("cp.async.bulk.shared::cluster.global.mbarrier::complete_tx::bytes "
                     "[%0], [%1], %2, [%3];"
                     :: "r"(dst), "l"(src), "r"(16384u), "r"(mb) : "memory");
    }

#pragma unroll
    for (int i = 0; i < 16; i++) {
        int s = tid + i * 256;
        int half = s >> 11, rem = s & 2047;
        int n = rem >> 5, m = rem & 31;
        sB4[n * 68 + half * 32 + m] = g_Wi[s];
    }
    __syncthreads();

    {
        uint32_t mb = smem_u32(&mbar[wid]);
        asm volatile(
            "{ .reg .pred p;\n"
            "W_%=: mbarrier.try_wait.parity.shared.b64 p, [%0], 0;\n"
            " @p bra D_%=;\n"
            " bra W_%=;\n"
            "D_%=: }"
            :: "r"(mb) : "memory");
    }
    __syncwarp();

    float acc[8][4];
#pragma unroll
    for (int nt = 0; nt < 8; nt++)
#pragma unroll
        for (int i = 0; i < 4; i++) acc[nt][i] = 0.f;

    const float* row0 = sXf + wid * 4096 + g * 256;
    const float* row1 = sXf + wid * 4096 + (g + 8) * 256;

    for (int c = 0; c < 8; c++) {
#pragma unroll
        for (int kk = 0; kk < 2; kk++) {
            const int kloc = c * 32 + kk * 16 + tig * 2;
            float2 a0 = *(const float2*)(row0 + kloc);
            float2 a4 = *(const float2*)(row0 + kloc + 8);
            float2 c0 = *(const float2*)(row1 + kloc);
            float2 c4 = *(const float2*)(row1 + kloc + 8);
            uint32_t ah[4], al[4];
            ah[0] = pack_bf16(a0.x, a0.y);
            ah[1] = pack_bf16(c0.x, c0.y);
            ah[2] = pack_bf16(a4.x, a4.y);
            ah[3] = pack_bf16(c4.x, c4.y);
            al[0] = pack_bf16(a0.x - bf16lo_val(ah[0]), a0.y - bf16hi_val(ah[0]));
            al[1] = pack_bf16(c0.x - bf16lo_val(ah[1]), c0.y - bf16hi_val(ah[1]));
            al[2] = pack_bf16(a4.x - bf16lo_val(ah[2]), a4.y - bf16hi_val(ah[2]));
            al[3] = pack_bf16(c4.x - bf16lo_val(ah[3]), c4.y - bf16hi_val(ah[3]));
            const int qidx = (c >> 2) * 32 + ((c & 3) * 2 + kk) * 4 + tig;
#pragma unroll
            for (int grp = 0; grp < 2; grp++) {
                const int nb = grp * 4;
                uint4 q0 = sB4[(nb * 8 +  0 + g) * 68 + qidx];
                uint4 q1 = sB4[(nb * 8 +  8 + g) * 68 + qidx];
                uint4 q2 = sB4[(nb * 8 + 16 + g) * 68 + qidx];
                uint4 q3 = sB4[(nb * 8 + 24 + g) * 68 + qidx];
                mma_bf16(acc[nb + 0], ah, q0.x, q0.y);
                mma_bf16(acc[nb + 1], ah, q1.x, q1.y);
                mma_bf16(acc[nb + 2], ah, q2.x, q2.y);
                mma_bf16(acc[nb + 3], ah, q3.x, q3.y);
                mma_bf16(acc[nb + 0], al, q0.x, q0.y);
                mma_bf16(acc[nb + 1], al, q1.x, q1.y);
                mma_bf16(acc[nb + 2], al, q2.x, q2.y);
                mma_bf16(acc[nb + 3], al, q3.x, q3.y);
                mma_bf16(acc[nb + 0], ah, q0.z, q0.w);
                mma_bf16(acc[nb + 1], ah, q1.z, q1.w);
                mma_bf16(acc[nb + 2], ah, q2.z, q2.w);
                mma_bf16(acc[nb + 3], ah, q3.z, q3.w);
            }
        }
    }

    // ---- epilogue: bias, e0/e1 reduce, fp32 + fp16 feature stores ----
    float e0a = 0.f, e1a = 0.f, e0b = 0.f, e1b = 0.f;
#pragma unroll
    for (int nt = 0; nt < 8; nt++) {
        int col = nt * 8 + tig * 2;
        float bi0 = __ldg(&b[col]);
        float bi1 = __ldg(&b[col + 1]);
        float at00 = __ldg(&att[col * 2 + 0]),   at01 = __ldg(&att[col * 2 + 1]);
        float at10 = __ldg(&att[(col + 1) * 2]), at11 = __ldg(&att[(col + 1) * 2 + 1]);
        acc[nt][0] += bi0; acc[nt][1] += bi1;
        acc[nt][2] += bi0; acc[nt][3] += bi1;
        e0a += acc[nt][0] * at00 + acc[nt][1] * at10;
        e1a += acc[nt][0] * at01 + acc[nt][1] * at11;
        e0b += acc[nt][2] * at00 + acc[nt][3] * at10;
        e1b += acc[nt][2] * at01 + acc[nt][3] * at11;
    }
#pragma unroll
    for (int o = 1; o <= 2; o <<= 1) {
        e0a += __shfl_xor_sync(0xffffffffu, e0a, o);
        e1a += __shfl_xor_sync(0xffffffffu, e1a, o);
        e0b += __shfl_xor_sync(0xffffffffu, e0b, o);
        e1b += __shfl_xor_sync(0xffffffffu, e1b, o);
    }
#pragma unroll
    for (int nt = 0; nt < 8; nt++) {
        int col = nt * 8 + tig * 2;
        *(float2*)&g_feature[(size_t)r0 * OUT_CH + col] = make_float2(acc[nt][0], acc[nt][1]);
        *(float2*)&g_feature[(size_t)r1 * OUT_CH + col] = make_float2(acc[nt][2], acc[nt][3]);
        g_feath[r0 * 32 + nt * 4 + tig] = pack_f16(acc[nt][0], acc[nt][1]);
        g_feath[r1 * 32 + nt * 4 + tig] = pack_f16(acc[nt][2], acc[nt][3]);
    }
    if (tig == 0) {
        g_e0[r0] = e0a; g_e1[r0] = e1a; g_es[r0] = __expf(lrelu(e0a + e1a));
        g_e0[r1] = e0b; g_e1[r1] = e1b; g_es[r1] = __expf(lrelu(e0b + e1b));
    }
}

// ------------- K2a: in-degree histogram ----------------------------------------
__global__ __launch_bounds__(256) void k_hist(const int* __restrict__ ei) {
    int e = blockIdx.x * 256 + threadIdx.x;
    if (e >= N_EDGES) return;
    atomicAdd(&g_cnt[__ldg(&ei[e])], 1);
}

// ------------- K2b1: per-block sums --------------------------------------------
__global__ __launch_bounds__(256) void k_scan1() {
    __shared__ int ws[8];
    const int t = threadIdx.x, lane = t & 31, w = t >> 5;
    const int i = blockIdx.x * 256 + t;
    int v = (i < N_NODES) ? g_cnt[i] : 0;
#pragma unroll
    for (int o = 16; o; o >>= 1) v += __shfl_xor_sync(0xffffffffu, v, o);
    if (lane == 0) ws[w] = v;
    __syncthreads();
    if (t == 0) {
        int s = 0;
#pragma unroll
        for (int j = 0; j < 8; j++) s += ws[j];
        g_bsum[blockIdx.x] = s;
    }
}

// ------------- K2b2: fused block-offset + local scan -> rowptr, cursor ---------
__global__ __launch_bounds__(256) void k_scan23() {
    __shared__ int ws[8];
    __shared__ int sboff;
    const int t = threadIdx.x, lane = t & 31, w = t >> 5;

    int v = (t < NB_SCAN && t < blockIdx.x) ? g_bsum[t] : 0;
#pragma unroll
    for (int o = 16; o; o >>= 1) v += __shfl_xor_sync(0xffffffffu, v, o);
    if (lane == 0) ws[w] = v;
    __syncthreads();
    if (t == 0) {
        int s = 0;
#pragma unroll
        for (int j = 0; j < 8; j++) s += ws[j];
        sboff = s;
    }
    __syncthreads();
    const int boff = sboff;
    __syncthreads();

    const int i = blockIdx.x * 256 + t;
    int c = (i < N_NODES) ? g_cnt[i] : 0;
    int inc = c;
#pragma unroll
    for (int o = 1; o < 32; o <<= 1) {
        int u = __shfl_up_sync(0xffffffffu, inc, o);
        if (lane >= o) inc += u;
    }
    if (lane == 31) ws[w] = inc;
    __syncthreads();
    if (w == 0) {
        int s = (lane < 8) ? ws[lane] : 0;
#pragma unroll
        for (int o = 1; o < 8; o <<= 1) {
            int u = __shfl_up_sync(0xffffffffu, s, o);
            if (lane >= o) s += u;
        }
        if (lane < 8) ws[lane] = s;
    }
    __syncthreads();
    int pos = boff + (w ? ws[w - 1] : 0) + inc - c;
    if (i < N_NODES) {
        g_rowptr[i] = pos;
        g_cursor[i] = pos;
    }
    if (blockIdx.x == 0 && t == 0) g_rowptr[N_NODES] = N_EDGES;
}

// ------------- K2c: scatter src indices into CSR slots -------------------------
__global__ __launch_bounds__(256) void k_scatter(const int* __restrict__ ei) {
    int e = blockIdx.x * 256 + threadIdx.x;
    if (e >= N_EDGES) return;
    int tar = __ldg(&ei[e]);
    int src = __ldg(&ei[N_EDGES + e]);
    int pos = atomicAdd(&g_cursor[tar], 1);
    g_csrc[pos] = src;
}

// ------------- K3: pull aggregation, half-warp per edge, fp16 gather -----------
// 16 lanes per edge; lane sl owns channels sl*4..sl*4+3 via one uint2 (4x fp16).
// Self term stays fp32. Register softmax denominator; no RED, no normalize pass.
__global__ __launch_bounds__(256) void k_agg(float* __restrict__ out) {
    const int warp = (blockIdx.x * 256 + threadIdx.x) >> 5;
    const int lane = threadIdx.x & 31;
    if (warp >= N_NODES) return;
    const int h  = lane >> 4;
    const int sl = lane & 15;
    const int n = warp;
    const int beg = g_rowptr[n];
    const int end = g_rowptr[n + 1];
    const float e0n = g_e0[n];
    const float es  = g_es[n];

    float4 fs = *(const float4*)&g_feature[(size_t)n * OUT_CH + sl * 4];
    const float w0 = (h == 0) ? es : 0.f;
    float ax = w0 * fs.x, ay = w0 * fs.y, az = w0 * fs.z, aw = w0 * fs.w;
    float dsum = w0;

    for (int j0 = beg; j0 < end; j0 += 32) {
        const int idx = j0 + lane;
        int src = 0;
        float ee = 0.f;
        if (idx < end) {
            src = __ldg(&g_csrc[idx]);
            ee  = __expf(lrelu(e0n + __ldg(&g_e1[src])));
        }
        int cnt = end - j0; if (cnt > 32) cnt = 32;
        const int np = (cnt + 1) >> 1;
#pragma unroll 4
        for (int jj = 0; jj < np; jj++) {
            const int j = jj * 2 + h;              // lanes >= cnt carry ee=0
            int   s = __shfl_sync(0xffffffffu, src, j);
            float w = __shfl_sync(0xffffffffu, ee,  j);
            uint2 pb = *(const uint2*)&g_feath[s * 32 + sl * 2];
            float2 f01 = __half22float2(*(const __half2*)&pb.x);
            float2 f23 = __half22float2(*(const __half2*)&pb.y);
            ax += w * f01.x;
            ay += w * f01.y;
            az += w * f23.x;
            aw += w * f23.y;
            dsum += w;
        }
    }
    ax += __shfl_xor_sync(0xffffffffu, ax, 16);
    ay += __shfl_xor_sync(0xffffffffu, ay, 16);
    az += __shfl_xor_sync(0xffffffffu, az, 16);
    aw += __shfl_xor_sync(0xffffffffu, aw, 16);
    dsum += __shfl_xor_sync(0xffffffffu, dsum, 16);
    if (h == 0) {
        const float rd = 1.0f / dsum;
        *(float4*)&out[(size_t)n * OUT_CH + sl * 4] =
            make_float4(ax * rd, ay * rd, az * rd, aw * rd);
    }
}

// -------------------------------------------------------------------------------
extern "C" void kernel_launch(void* const* d_in, const int* in_sizes, int n_in,
                              void* d_out, int out_size) {
    const float* x   = (const float*)d_in[0];
    const int*   ei  = (const int*)d_in[1];   // int32 (JAX x64 disabled)
    const float* W   = (const float*)d_in[2];
    const float* b   = (const float*)d_in[3];
    const float* att = (const float*)d_in[4];
    float* out = (float*)d_out;

    static cudaStream_t s2 = nullptr;
    static cudaEvent_t evF = nullptr, evJ = nullptr;
    if (s2 == nullptr) {
        cudaStreamCreate(&s2);
        cudaEventCreateWithFlags(&evF, cudaEventDisableTiming);
        cudaEventCreateWithFlags(&evJ, cudaEventDisableTiming);
    }
    cudaFuncSetAttribute(k_gemm_tc, cudaFuncAttributeMaxDynamicSharedMemorySize, DYN_BYTES);

    // fork edge chain onto s2; interleave issue order so gemm is the 4th launch
    // (the ncu window captures launch #4).
    cudaEventRecord(evF, 0);
    cudaStreamWaitEvent(s2, evF, 0);
    k_zero   <<<NB_SCAN, 256, 0, s2>>>();                       // 1
    k_wconv  <<<16, 256>>>(W);                                  // 2 (main)
    k_hist   <<<(N_EDGES + 255) / 256, 256, 0, s2>>>(ei);       // 3
    k_gemm_tc<<<(N_NODES + 127) / 128, 256, DYN_BYTES>>>(x, b, att);  // 4 (main)
    k_scan1  <<<NB_SCAN, 256, 0, s2>>>();                       // 5
    k_scan23 <<<NB_SCAN, 256, 0, s2>>>();                       // 6
    k_scatter<<<(N_EDGES + 255) / 256, 256, 0, s2>>>(ei);       // 7
    cudaEventRecord(evJ, s2);

    cudaStreamWaitEvent(0, evJ, 0);
    k_agg<<<(N_NODES * 32 + 255) / 256, 256>>>(out);            // 8
}